// round 10
// baseline (speedup 1.0000x reference)
#include <cuda_runtime.h>
#include <cstdint>

// ---------------------------------------------------------------------------
// SymmetrizeRotavg — converged scatter + instruction-lean periphery.
//   scaled[n]   = inv_lat[b(n)]^T @ forces[n]
//   acc[symm_map[n,o]] += rot[o] @ scaled[n]   (o = 0..O-1)
//   out[n]      = lat[b(n)]^T @ (acc[n] / O)
//
// Scatter pinned at the B300 spread-REDG floor: 50.3M red.v4 lanes x 1.29
// cyc/lane / 148 SMs ~= 245us @NAT (measured 1.28). R1-R9 findings:
//   - red.global.add.v4.f32: 16B/lane at scalar-lane cost; widest red
//   - float4 smem rot tiles = LDS.128 bank-conflict disaster (R3) -> scalar
//   - self-cleaning accumulator deletes all zeroing cost (R6)
//   - k_prep was LSU-issue bound (13 mem instrs/atom, issue 37.7%, DRAM 18%)
//     -> R10: 4 atoms/thread => 4 mem instrs/atom (float4 forces + 1 STG.128)
// ---------------------------------------------------------------------------

#define MAX_N (1 << 20)   // N = 1,048,576 for this problem
#define MAX_O 64

__device__ float4 g_scaled[MAX_N];
__device__ float4 g_acc[MAX_N];   // zero at load; re-zeroed by final each launch

// Stage 1: scaled = inv_lat^T f, 4 atoms/thread (A % 4 == 0 -> one lattice
// per thread). 3x LDG.128 forces + 9 broadcast LDG (shared by the 128
// consecutive threads with the same b) + 4x STG.128.
__global__ __launch_bounds__(256) void k_prep4(
    const float* __restrict__ inv_lat,   // (B,3,3)
    const float* __restrict__ forces,    // (N,3)
    int N4, int A)
{
    int q = blockIdx.x * blockDim.x + threadIdx.x;
    if (q >= N4) return;
    int n0 = q * 4;
    int b = n0 / A;

    const float4* f4 = reinterpret_cast<const float4*>(forces + (long long)n0 * 3);
    float4 a = f4[0];   // f0.x f0.y f0.z f1.x
    float4 c = f4[1];   // f1.y f1.z f2.x f2.y
    float4 d = f4[2];   // f2.z f3.x f3.y f3.z

    const float* M = inv_lat + 9 * b;   // M[j*3+i]
    float M00 = __ldg(M + 0), M01 = __ldg(M + 1), M02 = __ldg(M + 2);
    float M10 = __ldg(M + 3), M11 = __ldg(M + 4), M12 = __ldg(M + 5);
    float M20 = __ldg(M + 6), M21 = __ldg(M + 7), M22 = __ldg(M + 8);

    float fx[4] = { a.x, a.w, c.z, d.y };
    float fy[4] = { a.y, c.x, c.w, d.z };
    float fz[4] = { a.z, c.y, d.x, d.w };

#pragma unroll
    for (int t = 0; t < 4; t++) {
        float sx = M00 * fx[t] + M10 * fy[t] + M20 * fz[t];
        float sy = M01 * fx[t] + M11 * fy[t] + M21 * fz[t];
        float sz = M02 * fx[t] + M12 * fy[t] + M22 * fz[t];
        g_scaled[n0 + t] = make_float4(sx, sy, sz, 0.0f);
    }
}

// Scalar fallback prep.
__global__ __launch_bounds__(256) void k_prep1(
    const float* __restrict__ inv_lat,
    const float* __restrict__ forces,
    int N, int A)
{
    int n = blockIdx.x * blockDim.x + threadIdx.x;
    if (n >= N) return;
    int b = n / A;
    float f0 = forces[3 * n + 0];
    float f1 = forces[3 * n + 1];
    float f2 = forces[3 * n + 2];
    const float* M = inv_lat + 9 * b;
    float s0 = M[0] * f0 + M[3] * f1 + M[6] * f2;
    float s1 = M[1] * f0 + M[4] * f1 + M[7] * f2;
    float s2 = M[2] * f0 + M[5] * f1 + M[8] * f2;
    g_scaled[n] = make_float4(s0, s1, s2, 0.0f);
}

__device__ __forceinline__ void red_add_v4(float4* p, float x, float y, float z)
{
    asm volatile(
        "{\n\t"
        ".reg .u64 ga;\n\t"
        "cvta.to.global.u64 ga, %0;\n\t"
        "red.global.add.v4.f32 [ga], {%1, %2, %3, %4};\n\t"
        "}"
        :: "l"(p), "f"(x), "f"(y), "f"(z), "f"(0.0f)
        : "memory");
}

// Stage 2 (R1 body, floor-pinned): one thread = one n and 4 consecutive ops.
// Scalar smem rot loads (bank-conflict free), int4 smap load, 4x red.v4.
__global__ __launch_bounds__(256) void k_scatter4(
    const float* __restrict__ gops,   // (O,4,4)
    const int*   __restrict__ smap,   // (N,O)
    int N, int O)
{
    __shared__ float srot[MAX_O * 9];
    for (int t = threadIdx.x; t < O * 9; t += blockDim.x) {
        int o = t / 9;
        int e = t - o * 9;
        int i = e / 3;
        int j = e - i * 3;
        srot[t] = gops[o * 16 + i * 4 + j];
    }
    __syncthreads();

    int per_n = O >> 2;  // groups of 4 ops (O % 4 == 0)
    long long idx = (long long)blockIdx.x * blockDim.x + threadIdx.x;
    long long total = (long long)N * per_n;
    if (idx >= total) return;
    int n = (int)(idx / per_n);
    int k = (int)(idx - (long long)n * per_n);

    float4 s = g_scaled[n];
    int4 t4 = *reinterpret_cast<const int4*>(smap + (long long)n * O + k * 4);
    int tgt[4] = { t4.x, t4.y, t4.z, t4.w };

#pragma unroll
    for (int r = 0; r < 4; r++) {
        int o = k * 4 + r;
        const float* R = srot + o * 9;   // R[i*3+j]
        float x = R[0] * s.x + R[1] * s.y + R[2] * s.z;
        float y = R[3] * s.x + R[4] * s.y + R[5] * s.z;
        float z = R[6] * s.x + R[7] * s.y + R[8] * s.z;
        red_add_v4(&g_acc[tgt[r]], x, y, z);
    }
}

// Fallback (O not a multiple of 4): one thread per (n,o).
__global__ __launch_bounds__(256) void k_scatter1(
    const float* __restrict__ gops,
    const int*   __restrict__ smap,
    int N, int O)
{
    __shared__ float srot[MAX_O * 9];
    for (int t = threadIdx.x; t < O * 9; t += blockDim.x) {
        int o = t / 9;
        int e = t - o * 9;
        int i = e / 3;
        int j = e - i * 3;
        srot[t] = gops[o * 16 + i * 4 + j];
    }
    __syncthreads();

    long long idx = (long long)blockIdx.x * blockDim.x + threadIdx.x;
    long long total = (long long)N * O;
    if (idx >= total) return;
    int n = (int)(idx / O);
    int o = (int)(idx - (long long)n * O);

    float4 s = g_scaled[n];
    int tgt = smap[(long long)n * O + o];
    const float* R = srot + o * 9;
    float x = R[0] * s.x + R[1] * s.y + R[2] * s.z;
    float y = R[3] * s.x + R[4] * s.y + R[5] * s.z;
    float z = R[6] * s.x + R[7] * s.y + R[8] * s.z;
    red_add_v4(&g_acc[tgt], x, y, z);
}

// Stage 3: out = lat^T (acc / O), 2 atoms per thread, float2 out stores.
// Self-cleaning: re-zeroes g_acc after reading (next launch needs no memset;
// zero lines stay dirty in L2 where the next replay's atomics hit).
__global__ __launch_bounds__(256) void k_final2(
    const float* __restrict__ lat,
    float* __restrict__ out,
    int N2, int A, float inv_count)
{
    int q = blockIdx.x * blockDim.x + threadIdx.x;
    if (q >= N2) return;
    int n0 = q * 2;
    int b = n0 / A;
    const float* L = lat + 9 * b;   // L[j*3+i]
    float L00 = __ldg(L + 0), L01 = __ldg(L + 1), L02 = __ldg(L + 2);
    float L10 = __ldg(L + 3), L11 = __ldg(L + 4), L12 = __ldg(L + 5);
    float L20 = __ldg(L + 6), L21 = __ldg(L + 7), L22 = __ldg(L + 8);

    float4 a0 = g_acc[n0 + 0];
    float4 a1 = g_acc[n0 + 1];
    float4 zero = make_float4(0.f, 0.f, 0.f, 0.f);
    g_acc[n0 + 0] = zero;            // self-clean for next launch
    g_acc[n0 + 1] = zero;

    float s00 = a0.x * inv_count, s01 = a0.y * inv_count, s02 = a0.z * inv_count;
    float s10 = a1.x * inv_count, s11 = a1.y * inv_count, s12 = a1.z * inv_count;

    float r0 = L00 * s00 + L10 * s01 + L20 * s02;
    float r1 = L01 * s00 + L11 * s01 + L21 * s02;
    float r2 = L02 * s00 + L12 * s01 + L22 * s02;
    float r3 = L00 * s10 + L10 * s11 + L20 * s12;
    float r4 = L01 * s10 + L11 * s11 + L21 * s12;
    float r5 = L02 * s10 + L12 * s11 + L22 * s12;

    float2* dst = reinterpret_cast<float2*>(out + (long long)q * 6);
    dst[0] = make_float2(r0, r1);
    dst[1] = make_float2(r2, r3);
    dst[2] = make_float2(r4, r5);
}

// Scalar fallback final (also self-cleaning).
__global__ __launch_bounds__(256) void k_final1(
    const float* __restrict__ lat,
    float* __restrict__ out,
    int N, int A, float inv_count)
{
    int n = blockIdx.x * blockDim.x + threadIdx.x;
    if (n >= N) return;
    int b = n / A;
    float4 a = g_acc[n];
    g_acc[n] = make_float4(0.f, 0.f, 0.f, 0.f);
    float s0 = a.x * inv_count;
    float s1 = a.y * inv_count;
    float s2 = a.z * inv_count;
    const float* L = lat + 9 * b;
    out[3 * n + 0] = L[0] * s0 + L[3] * s1 + L[6] * s2;
    out[3 * n + 1] = L[1] * s0 + L[4] * s1 + L[7] * s2;
    out[3 * n + 2] = L[2] * s0 + L[5] * s1 + L[8] * s2;
}

extern "C" void kernel_launch(void* const* d_in, const int* in_sizes, int n_in,
                              void* d_out, int out_size)
{
    const float* lattices     = (const float*)d_in[0];  // (B,3,3)
    const float* inv_lattices = (const float*)d_in[1];  // (B,3,3)
    const float* forces       = (const float*)d_in[2];  // (N,3)
    // d_in[3] = num_atoms (int64, uniform A)
    const float* general_ops  = (const float*)d_in[4];  // (O,4,4)
    const int*   symm_map     = (const int*)d_in[5];    // (N,O)
    // d_in[6] = num_general_ops (int64, uniform O)

    int B = in_sizes[0] / 9;
    int N = in_sizes[2] / 3;
    int O = in_sizes[4] / 16;
    int A = N / B;

    float* out = (float*)d_out;
    const int TPB = 256;

    if ((A & 3) == 0 && (N & 3) == 0) {
        int N4 = N / 4;
        k_prep4<<<(N4 + TPB - 1) / TPB, TPB>>>(inv_lattices, forces, N4, A);
    } else {
        k_prep1<<<(N + TPB - 1) / TPB, TPB>>>(inv_lattices, forces, N, A);
    }

    if ((O & 3) == 0) {
        long long total = (long long)N * (O >> 2);
        int blocks = (int)((total + TPB - 1) / TPB);
        k_scatter4<<<blocks, TPB>>>(general_ops, symm_map, N, O);
    } else {
        long long total = (long long)N * O;
        int blocks = (int)((total + TPB - 1) / TPB);
        k_scatter1<<<blocks, TPB>>>(general_ops, symm_map, N, O);
    }

    float inv_count = 1.0f / (float)O;
    if ((A & 1) == 0 && (N & 1) == 0) {
        int N2 = N / 2;
        k_final2<<<(N2 + TPB - 1) / TPB, TPB>>>(lattices, out, N2, A, inv_count);
    } else {
        k_final1<<<(N + TPB - 1) / TPB, TPB>>>(lattices, out, N, A, inv_count);
    }
}

// round 11
// speedup vs baseline: 1.0201x; 1.0201x over previous
#include <cuda_runtime.h>
#include <cstdint>

// ---------------------------------------------------------------------------
// SymmetrizeRotavg — FINAL (R1 configuration, best measured: 260.6us).
//   scaled[n]   = inv_lat[b(n)]^T @ forces[n]
//   acc[symm_map[n,o]] += rot[o] @ scaled[n]   (o = 0..O-1)
//   out[n]      = lat[b(n)]^T @ (acc[n] / O)
//
// The scatter is pinned at the B300 spread-REDG hardware floor:
//   N*O = 50.3M red.global.add.v4.f32 lanes x 1.29 cyc/lane / 148 SMs
//   ~= 245us @NAT (measured 1.28 cyc/lane).
// Session findings (R1-R10):
//   - red.v4 moves 16B/lane at scalar-lane cost — widest available reduction
//   - lane count is algorithmically irreducible (random map: inversion costs
//     an equal scatter; dedup rate ~0.1%; fp16 atomics break the 1e-3 bound)
//   - float4 smem rot tiles = LDS.128 bank-conflict disaster (+170us, R3)
//   - coarsening the short memory kernels (4 atoms/thread) LOSES: thread
//     count / latency hiding beats instructions-per-thread (R3, R7, R10)
//   - prep/zero/final variants all land within +-1.2us noise of this form
// ---------------------------------------------------------------------------

#define MAX_N (1 << 20)   // N = 1,048,576 for this problem
#define MAX_O 64

__device__ float4 g_scaled[MAX_N];
__device__ float4 g_acc[MAX_N];

// Stage 1: scaled = inv_lat^T f ; zero the accumulator (every launch, so
// graph replays are deterministic). One atom per thread (max threads).
__global__ __launch_bounds__(256) void k_prep(
    const float* __restrict__ inv_lat,
    const float* __restrict__ forces,
    int N, int A)
{
    int n = blockIdx.x * blockDim.x + threadIdx.x;
    if (n >= N) return;
    int b = n / A;
    float f0 = forces[3 * n + 0];
    float f1 = forces[3 * n + 1];
    float f2 = forces[3 * n + 2];
    const float* M = inv_lat + 9 * b;   // M[j*3+i]
    float s0 = M[0] * f0 + M[3] * f1 + M[6] * f2;
    float s1 = M[1] * f0 + M[4] * f1 + M[7] * f2;
    float s2 = M[2] * f0 + M[5] * f1 + M[8] * f2;
    g_scaled[n] = make_float4(s0, s1, s2, 0.0f);
    g_acc[n]    = make_float4(0.0f, 0.0f, 0.0f, 0.0f);
}

__device__ __forceinline__ void red_add_v4(float4* p, float x, float y, float z)
{
    asm volatile(
        "{\n\t"
        ".reg .u64 ga;\n\t"
        "cvta.to.global.u64 ga, %0;\n\t"
        "red.global.add.v4.f32 [ga], {%1, %2, %3, %4};\n\t"
        "}"
        :: "l"(p), "f"(x), "f"(y), "f"(z), "f"(0.0f)
        : "memory");
}

// Stage 2 (floor-pinned): one thread = one n and 4 consecutive ops.
// Scalar smem rot loads (bank-conflict free), coalesced int4 smap load,
// 4x red.global.add.v4.f32 into the L2-resident accumulator.
__global__ __launch_bounds__(256) void k_scatter4(
    const float* __restrict__ gops,   // (O,4,4)
    const int*   __restrict__ smap,   // (N,O)
    int N, int O)
{
    __shared__ float srot[MAX_O * 9];
    for (int t = threadIdx.x; t < O * 9; t += blockDim.x) {
        int o = t / 9;
        int e = t - o * 9;
        int i = e / 3;
        int j = e - i * 3;
        srot[t] = gops[o * 16 + i * 4 + j];
    }
    __syncthreads();

    int per_n = O >> 2;  // groups of 4 ops (O % 4 == 0)
    long long idx = (long long)blockIdx.x * blockDim.x + threadIdx.x;
    long long total = (long long)N * per_n;
    if (idx >= total) return;
    int n = (int)(idx / per_n);
    int k = (int)(idx - (long long)n * per_n);

    float4 s = g_scaled[n];
    int4 t4 = *reinterpret_cast<const int4*>(smap + (long long)n * O + k * 4);
    int tgt[4] = { t4.x, t4.y, t4.z, t4.w };

#pragma unroll
    for (int r = 0; r < 4; r++) {
        int o = k * 4 + r;
        const float* R = srot + o * 9;   // R[i*3+j]
        float x = R[0] * s.x + R[1] * s.y + R[2] * s.z;
        float y = R[3] * s.x + R[4] * s.y + R[5] * s.z;
        float z = R[6] * s.x + R[7] * s.y + R[8] * s.z;
        red_add_v4(&g_acc[tgt[r]], x, y, z);
    }
}

// Fallback (O not a multiple of 4): one thread per (n,o).
__global__ __launch_bounds__(256) void k_scatter1(
    const float* __restrict__ gops,
    const int*   __restrict__ smap,
    int N, int O)
{
    __shared__ float srot[MAX_O * 9];
    for (int t = threadIdx.x; t < O * 9; t += blockDim.x) {
        int o = t / 9;
        int e = t - o * 9;
        int i = e / 3;
        int j = e - i * 3;
        srot[t] = gops[o * 16 + i * 4 + j];
    }
    __syncthreads();

    long long idx = (long long)blockIdx.x * blockDim.x + threadIdx.x;
    long long total = (long long)N * O;
    if (idx >= total) return;
    int n = (int)(idx / O);
    int o = (int)(idx - (long long)n * O);

    float4 s = g_scaled[n];
    int tgt = smap[(long long)n * O + o];
    const float* R = srot + o * 9;
    float x = R[0] * s.x + R[1] * s.y + R[2] * s.z;
    float y = R[3] * s.x + R[4] * s.y + R[5] * s.z;
    float z = R[6] * s.x + R[7] * s.y + R[8] * s.z;
    red_add_v4(&g_acc[tgt], x, y, z);
}

// Stage 3: out = lat^T (acc / O). One atom per thread (max threads; the
// acc float4 load is L2-hot from the atomics).
__global__ __launch_bounds__(256) void k_final(
    const float* __restrict__ lat,
    float* __restrict__ out,
    int N, int A, float inv_count)
{
    int n = blockIdx.x * blockDim.x + threadIdx.x;
    if (n >= N) return;
    int b = n / A;
    float4 a = g_acc[n];
    float s0 = a.x * inv_count;
    float s1 = a.y * inv_count;
    float s2 = a.z * inv_count;
    const float* L = lat + 9 * b;   // L[j*3+i]
    out[3 * n + 0] = L[0] * s0 + L[3] * s1 + L[6] * s2;
    out[3 * n + 1] = L[1] * s0 + L[4] * s1 + L[7] * s2;
    out[3 * n + 2] = L[2] * s0 + L[5] * s1 + L[8] * s2;
}

extern "C" void kernel_launch(void* const* d_in, const int* in_sizes, int n_in,
                              void* d_out, int out_size)
{
    const float* lattices     = (const float*)d_in[0];  // (B,3,3)
    const float* inv_lattices = (const float*)d_in[1];  // (B,3,3)
    const float* forces       = (const float*)d_in[2];  // (N,3)
    // d_in[3] = num_atoms (int64, uniform A)
    const float* general_ops  = (const float*)d_in[4];  // (O,4,4)
    const int*   symm_map     = (const int*)d_in[5];    // (N,O)
    // d_in[6] = num_general_ops (int64, uniform O)

    int B = in_sizes[0] / 9;
    int N = in_sizes[2] / 3;
    int O = in_sizes[4] / 16;
    int A = N / B;

    float* out = (float*)d_out;

    const int TPB = 256;
    int blocks_n = (N + TPB - 1) / TPB;

    k_prep<<<blocks_n, TPB>>>(inv_lattices, forces, N, A);

    if ((O & 3) == 0) {
        long long total = (long long)N * (O >> 2);
        int blocks = (int)((total + TPB - 1) / TPB);
        k_scatter4<<<blocks, TPB>>>(general_ops, symm_map, N, O);
    } else {
        long long total = (long long)N * O;
        int blocks = (int)((total + TPB - 1) / TPB);
        k_scatter1<<<blocks, TPB>>>(general_ops, symm_map, N, O);
    }

    k_final<<<blocks_n, TPB>>>(lattices, out, N, A, 1.0f / (float)O);
}

// round 12
// speedup vs baseline: 1.0301x; 1.0098x over previous
#include <cuda_runtime.h>
#include <cstdint>

// ---------------------------------------------------------------------------
// SymmetrizeRotavg — converged R1 configuration (best: 260.1us) with the
// scatter's runtime 64-bit division templated away (PER_N compile-time).
//   scaled[n]   = inv_lat[b(n)]^T @ forces[n]
//   acc[symm_map[n,o]] += rot[o] @ scaled[n]   (o = 0..O-1)
//   out[n]      = lat[b(n)]^T @ (acc[n] / O)
//
// Scatter pinned at the B300 spread-REDG hardware floor:
//   N*O = 50.3M red.global.add.v4.f32 lanes x 1.29 cyc/lane / 148 SMs
//   ~= 245us @NAT (measured 1.28 cyc/lane).
// Session findings (R1-R11):
//   - red.v4 moves 16B/lane at scalar-lane cost — widest available reduction
//   - lane count algorithmically irreducible (random map; inversion costs an
//     equal scatter; dedup ~0.1%; fp16 atomics break the 1e-3 bound)
//   - float4 smem rot tiles = LDS.128 bank-conflict disaster (+170us, R3)
//   - coarsening short memory kernels LOSES (R3/R7/R10): thread count and
//     latency hiding beat instructions-per-thread
//   - ncu periphery durations are cache-flush-inflated; trust totals only
// ---------------------------------------------------------------------------

#define MAX_N (1 << 20)   // N = 1,048,576 for this problem
#define MAX_O 64

__device__ float4 g_scaled[MAX_N];
__device__ float4 g_acc[MAX_N];

// Stage 1: scaled = inv_lat^T f ; zero the accumulator (every launch, so
// graph replays are deterministic). One atom per thread.
__global__ __launch_bounds__(256) void k_prep(
    const float* __restrict__ inv_lat,
    const float* __restrict__ forces,
    int N, int A)
{
    int n = blockIdx.x * blockDim.x + threadIdx.x;
    if (n >= N) return;
    int b = n / A;
    float f0 = forces[3 * n + 0];
    float f1 = forces[3 * n + 1];
    float f2 = forces[3 * n + 2];
    const float* M = inv_lat + 9 * b;   // M[j*3+i]
    float s0 = M[0] * f0 + M[3] * f1 + M[6] * f2;
    float s1 = M[1] * f0 + M[4] * f1 + M[7] * f2;
    float s2 = M[2] * f0 + M[5] * f1 + M[8] * f2;
    g_scaled[n] = make_float4(s0, s1, s2, 0.0f);
    g_acc[n]    = make_float4(0.0f, 0.0f, 0.0f, 0.0f);
}

__device__ __forceinline__ void red_add_v4(float4* p, float x, float y, float z)
{
    asm volatile(
        "{\n\t"
        ".reg .u64 ga;\n\t"
        "cvta.to.global.u64 ga, %0;\n\t"
        "red.global.add.v4.f32 [ga], {%1, %2, %3, %4};\n\t"
        "}"
        :: "l"(p), "f"(x), "f"(y), "f"(z), "f"(0.0f)
        : "memory");
}

// Stage 2 (floor-pinned, R1 body): one thread = one n and 4 consecutive ops.
// PER_N is compile-time so idx/PER_N is a mul-shift (R1 had a runtime 64-bit
// division here). Scalar smem rot loads (bank-conflict free), int4 smap load.
template<int PER_N>
__global__ __launch_bounds__(256) void k_scatterT(
    const float* __restrict__ gops,   // (O,4,4)
    const int*   __restrict__ smap,   // (N,O)
    int N, int O)
{
    __shared__ float srot[MAX_O * 9];
    for (int t = threadIdx.x; t < O * 9; t += blockDim.x) {
        int o = t / 9;
        int e = t - o * 9;
        int i = e / 3;
        int j = e - i * 3;
        srot[t] = gops[o * 16 + i * 4 + j];
    }
    __syncthreads();

    long long idx = (long long)blockIdx.x * blockDim.x + threadIdx.x;
    long long total = (long long)N * PER_N;
    if (idx >= total) return;
    int n = (int)(idx / PER_N);            // compile-time divisor -> mul-shift
    int k = (int)(idx - (long long)n * PER_N);

    float4 s = g_scaled[n];
    int4 t4 = *reinterpret_cast<const int4*>(smap + (long long)n * O + k * 4);
    int tgt[4] = { t4.x, t4.y, t4.z, t4.w };

#pragma unroll
    for (int r = 0; r < 4; r++) {
        int o = k * 4 + r;
        const float* R = srot + o * 9;   // R[i*3+j]
        float x = R[0] * s.x + R[1] * s.y + R[2] * s.z;
        float y = R[3] * s.x + R[4] * s.y + R[5] * s.z;
        float z = R[6] * s.x + R[7] * s.y + R[8] * s.z;
        red_add_v4(&g_acc[tgt[r]], x, y, z);
    }
}

// Runtime-O variant (O multiple of 4 but not 32/48/64).
__global__ __launch_bounds__(256) void k_scatter4(
    const float* __restrict__ gops,
    const int*   __restrict__ smap,
    int N, int O)
{
    __shared__ float srot[MAX_O * 9];
    for (int t = threadIdx.x; t < O * 9; t += blockDim.x) {
        int o = t / 9;
        int e = t - o * 9;
        int i = e / 3;
        int j = e - i * 3;
        srot[t] = gops[o * 16 + i * 4 + j];
    }
    __syncthreads();

    int per_n = O >> 2;
    long long idx = (long long)blockIdx.x * blockDim.x + threadIdx.x;
    long long total = (long long)N * per_n;
    if (idx >= total) return;
    int n = (int)(idx / per_n);
    int k = (int)(idx - (long long)n * per_n);

    float4 s = g_scaled[n];
    int4 t4 = *reinterpret_cast<const int4*>(smap + (long long)n * O + k * 4);
    int tgt[4] = { t4.x, t4.y, t4.z, t4.w };

#pragma unroll
    for (int r = 0; r < 4; r++) {
        int o = k * 4 + r;
        const float* R = srot + o * 9;
        float x = R[0] * s.x + R[1] * s.y + R[2] * s.z;
        float y = R[3] * s.x + R[4] * s.y + R[5] * s.z;
        float z = R[6] * s.x + R[7] * s.y + R[8] * s.z;
        red_add_v4(&g_acc[tgt[r]], x, y, z);
    }
}

// Fallback (O not a multiple of 4): one thread per (n,o).
__global__ __launch_bounds__(256) void k_scatter1(
    const float* __restrict__ gops,
    const int*   __restrict__ smap,
    int N, int O)
{
    __shared__ float srot[MAX_O * 9];
    for (int t = threadIdx.x; t < O * 9; t += blockDim.x) {
        int o = t / 9;
        int e = t - o * 9;
        int i = e / 3;
        int j = e - i * 3;
        srot[t] = gops[o * 16 + i * 4 + j];
    }
    __syncthreads();

    long long idx = (long long)blockIdx.x * blockDim.x + threadIdx.x;
    long long total = (long long)N * O;
    if (idx >= total) return;
    int n = (int)(idx / O);
    int o = (int)(idx - (long long)n * O);

    float4 s = g_scaled[n];
    int tgt = smap[(long long)n * O + o];
    const float* R = srot + o * 9;
    float x = R[0] * s.x + R[1] * s.y + R[2] * s.z;
    float y = R[3] * s.x + R[4] * s.y + R[5] * s.z;
    float z = R[6] * s.x + R[7] * s.y + R[8] * s.z;
    red_add_v4(&g_acc[tgt], x, y, z);
}

// Stage 3: out = lat^T (acc / O). One atom per thread (acc is L2-hot).
__global__ __launch_bounds__(256) void k_final(
    const float* __restrict__ lat,
    float* __restrict__ out,
    int N, int A, float inv_count)
{
    int n = blockIdx.x * blockDim.x + threadIdx.x;
    if (n >= N) return;
    int b = n / A;
    float4 a = g_acc[n];
    float s0 = a.x * inv_count;
    float s1 = a.y * inv_count;
    float s2 = a.z * inv_count;
    const float* L = lat + 9 * b;   // L[j*3+i]
    out[3 * n + 0] = L[0] * s0 + L[3] * s1 + L[6] * s2;
    out[3 * n + 1] = L[1] * s0 + L[4] * s1 + L[7] * s2;
    out[3 * n + 2] = L[2] * s0 + L[5] * s1 + L[8] * s2;
}

extern "C" void kernel_launch(void* const* d_in, const int* in_sizes, int n_in,
                              void* d_out, int out_size)
{
    const float* lattices     = (const float*)d_in[0];  // (B,3,3)
    const float* inv_lattices = (const float*)d_in[1];  // (B,3,3)
    const float* forces       = (const float*)d_in[2];  // (N,3)
    // d_in[3] = num_atoms (int64, uniform A)
    const float* general_ops  = (const float*)d_in[4];  // (O,4,4)
    const int*   symm_map     = (const int*)d_in[5];    // (N,O)
    // d_in[6] = num_general_ops (int64, uniform O)

    int B = in_sizes[0] / 9;
    int N = in_sizes[2] / 3;
    int O = in_sizes[4] / 16;
    int A = N / B;

    float* out = (float*)d_out;

    const int TPB = 256;
    int blocks_n = (N + TPB - 1) / TPB;

    k_prep<<<blocks_n, TPB>>>(inv_lattices, forces, N, A);

    if (O == 48) {
        long long total = (long long)N * 12;
        int blocks = (int)((total + TPB - 1) / TPB);
        k_scatterT<12><<<blocks, TPB>>>(general_ops, symm_map, N, O);
    } else if (O == 32) {
        long long total = (long long)N * 8;
        int blocks = (int)((total + TPB - 1) / TPB);
        k_scatterT<8><<<blocks, TPB>>>(general_ops, symm_map, N, O);
    } else if (O == 64) {
        long long total = (long long)N * 16;
        int blocks = (int)((total + TPB - 1) / TPB);
        k_scatterT<16><<<blocks, TPB>>>(general_ops, symm_map, N, O);
    } else if ((O & 3) == 0) {
        long long total = (long long)N * (O >> 2);
        int blocks = (int)((total + TPB - 1) / TPB);
        k_scatter4<<<blocks, TPB>>>(general_ops, symm_map, N, O);
    } else {
        long long total = (long long)N * O;
        int blocks = (int)((total + TPB - 1) / TPB);
        k_scatter1<<<blocks, TPB>>>(general_ops, symm_map, N, O);
    }

    k_final<<<blocks_n, TPB>>>(lattices, out, N, A, 1.0f / (float)O);
}

// round 13
// speedup vs baseline: 1.0428x; 1.0123x over previous
#include <cuda_runtime.h>
#include <cstdint>

// ---------------------------------------------------------------------------
// SymmetrizeRotavg — converged form (best: 257.6us at R12).
//   scaled[n]   = inv_lat[b(n)]^T @ forces[n]
//   acc[symm_map[n,o]] += rot[o] @ scaled[n]   (o = 0..O-1)
//   out[n]      = lat[b(n)]^T @ (acc[n] / O)
//
// Scatter at 98.9% of the B300 spread-REDG hardware floor:
//   N*O = 50.3M red.global.add.v4.f32 lanes x 1.29 cyc/lane / 148 SMs.
// Session findings (R1-R12):
//   - red.v4 moves 16B/lane at scalar-lane cost — widest available reduction
//   - lane count algorithmically irreducible (random map)
//   - float4 smem rot tiles = LDS.128 bank-conflict disaster (+170us, R3)
//   - coarsening short memory kernels LOSES (R3/R7/R10)
//   - compile-time divisors on the scatter path: real -2.5us win (R12)
//   - R13: O fully templated -> constant-mul smap addressing + unrolled
//     srot staging (no division chains at block start)
// ---------------------------------------------------------------------------

#define MAX_N (1 << 20)   // N = 1,048,576 for this problem
#define MAX_O 64

__device__ float4 g_scaled[MAX_N];
__device__ float4 g_acc[MAX_N];

// Stage 1: scaled = inv_lat^T f ; zero the accumulator (every launch, so
// graph replays are deterministic). One atom per thread.
__global__ __launch_bounds__(256) void k_prep(
    const float* __restrict__ inv_lat,
    const float* __restrict__ forces,
    int N, int A)
{
    int n = blockIdx.x * blockDim.x + threadIdx.x;
    if (n >= N) return;
    int b = n / A;
    float f0 = forces[3 * n + 0];
    float f1 = forces[3 * n + 1];
    float f2 = forces[3 * n + 2];
    const float* M = inv_lat + 9 * b;   // M[j*3+i]
    float s0 = M[0] * f0 + M[3] * f1 + M[6] * f2;
    float s1 = M[1] * f0 + M[4] * f1 + M[7] * f2;
    float s2 = M[2] * f0 + M[5] * f1 + M[8] * f2;
    g_scaled[n] = make_float4(s0, s1, s2, 0.0f);
    g_acc[n]    = make_float4(0.0f, 0.0f, 0.0f, 0.0f);
}

__device__ __forceinline__ void red_add_v4(float4* p, float x, float y, float z)
{
    asm volatile(
        "{\n\t"
        ".reg .u64 ga;\n\t"
        "cvta.to.global.u64 ga, %0;\n\t"
        "red.global.add.v4.f32 [ga], {%1, %2, %3, %4};\n\t"
        "}"
        :: "l"(p), "f"(x), "f"(y), "f"(z), "f"(0.0f)
        : "memory");
}

// Stage 2 (floor-pinned): one thread = one n and 4 consecutive ops.
// O is a compile-time constant: idx/PER_N is a mul-shift, the smap address
// n*O is a constant-mul IMAD, and the srot staging loop is fully unrolled.
// Scalar smem rot loads (bank-conflict free), coalesced int4 smap load.
template<int O>
__global__ __launch_bounds__(256) void k_scatterT(
    const float* __restrict__ gops,   // (O,4,4)
    const int*   __restrict__ smap,   // (N,O)
    int N)
{
    constexpr int PER_N = O / 4;
    __shared__ float srot[O * 9];
    // 256 threads, O*9 <= 576 elements: <= 3 fully-unrolled iterations.
#pragma unroll
    for (int t = threadIdx.x; t < O * 9; t += 256) {
        int o = t / 9;
        int e = t - o * 9;
        int i = e / 3;
        int j = e - i * 3;
        srot[t] = __ldg(gops + o * 16 + i * 4 + j);
    }
    __syncthreads();

    long long idx = (long long)blockIdx.x * blockDim.x + threadIdx.x;
    long long total = (long long)N * PER_N;
    if (idx >= total) return;
    int n = (int)(idx / PER_N);            // compile-time divisor -> mul-shift
    int k = (int)(idx - (long long)n * PER_N);

    float4 s = g_scaled[n];
    int4 t4 = *reinterpret_cast<const int4*>(smap + (long long)n * O + k * 4);
    int tgt[4] = { t4.x, t4.y, t4.z, t4.w };

#pragma unroll
    for (int r = 0; r < 4; r++) {
        int o = k * 4 + r;
        const float* R = srot + o * 9;   // R[i*3+j]
        float x = R[0] * s.x + R[1] * s.y + R[2] * s.z;
        float y = R[3] * s.x + R[4] * s.y + R[5] * s.z;
        float z = R[6] * s.x + R[7] * s.y + R[8] * s.z;
        red_add_v4(&g_acc[tgt[r]], x, y, z);
    }
}

// Runtime-O variant (O multiple of 4 but not 32/48/64).
__global__ __launch_bounds__(256) void k_scatter4(
    const float* __restrict__ gops,
    const int*   __restrict__ smap,
    int N, int O)
{
    __shared__ float srot[MAX_O * 9];
    for (int t = threadIdx.x; t < O * 9; t += blockDim.x) {
        int o = t / 9;
        int e = t - o * 9;
        int i = e / 3;
        int j = e - i * 3;
        srot[t] = gops[o * 16 + i * 4 + j];
    }
    __syncthreads();

    int per_n = O >> 2;
    long long idx = (long long)blockIdx.x * blockDim.x + threadIdx.x;
    long long total = (long long)N * per_n;
    if (idx >= total) return;
    int n = (int)(idx / per_n);
    int k = (int)(idx - (long long)n * per_n);

    float4 s = g_scaled[n];
    int4 t4 = *reinterpret_cast<const int4*>(smap + (long long)n * O + k * 4);
    int tgt[4] = { t4.x, t4.y, t4.z, t4.w };

#pragma unroll
    for (int r = 0; r < 4; r++) {
        int o = k * 4 + r;
        const float* R = srot + o * 9;
        float x = R[0] * s.x + R[1] * s.y + R[2] * s.z;
        float y = R[3] * s.x + R[4] * s.y + R[5] * s.z;
        float z = R[6] * s.x + R[7] * s.y + R[8] * s.z;
        red_add_v4(&g_acc[tgt[r]], x, y, z);
    }
}

// Fallback (O not a multiple of 4): one thread per (n,o).
__global__ __launch_bounds__(256) void k_scatter1(
    const float* __restrict__ gops,
    const int*   __restrict__ smap,
    int N, int O)
{
    __shared__ float srot[MAX_O * 9];
    for (int t = threadIdx.x; t < O * 9; t += blockDim.x) {
        int o = t / 9;
        int e = t - o * 9;
        int i = e / 3;
        int j = e - i * 3;
        srot[t] = gops[o * 16 + i * 4 + j];
    }
    __syncthreads();

    long long idx = (long long)blockIdx.x * blockDim.x + threadIdx.x;
    long long total = (long long)N * O;
    if (idx >= total) return;
    int n = (int)(idx / O);
    int o = (int)(idx - (long long)n * O);

    float4 s = g_scaled[n];
    int tgt = smap[(long long)n * O + o];
    const float* R = srot + o * 9;
    float x = R[0] * s.x + R[1] * s.y + R[2] * s.z;
    float y = R[3] * s.x + R[4] * s.y + R[5] * s.z;
    float z = R[6] * s.x + R[7] * s.y + R[8] * s.z;
    red_add_v4(&g_acc[tgt], x, y, z);
}

// Stage 3: out = lat^T (acc / O). One atom per thread (acc is L2-hot).
__global__ __launch_bounds__(256) void k_final(
    const float* __restrict__ lat,
    float* __restrict__ out,
    int N, int A, float inv_count)
{
    int n = blockIdx.x * blockDim.x + threadIdx.x;
    if (n >= N) return;
    int b = n / A;
    float4 a = g_acc[n];
    float s0 = a.x * inv_count;
    float s1 = a.y * inv_count;
    float s2 = a.z * inv_count;
    const float* L = lat + 9 * b;   // L[j*3+i]
    out[3 * n + 0] = L[0] * s0 + L[3] * s1 + L[6] * s2;
    out[3 * n + 1] = L[1] * s0 + L[4] * s1 + L[7] * s2;
    out[3 * n + 2] = L[2] * s0 + L[5] * s1 + L[8] * s2;
}

extern "C" void kernel_launch(void* const* d_in, const int* in_sizes, int n_in,
                              void* d_out, int out_size)
{
    const float* lattices     = (const float*)d_in[0];  // (B,3,3)
    const float* inv_lattices = (const float*)d_in[1];  // (B,3,3)
    const float* forces       = (const float*)d_in[2];  // (N,3)
    // d_in[3] = num_atoms (int64, uniform A)
    const float* general_ops  = (const float*)d_in[4];  // (O,4,4)
    const int*   symm_map     = (const int*)d_in[5];    // (N,O)
    // d_in[6] = num_general_ops (int64, uniform O)

    int B = in_sizes[0] / 9;
    int N = in_sizes[2] / 3;
    int O = in_sizes[4] / 16;
    int A = N / B;

    float* out = (float*)d_out;

    const int TPB = 256;
    int blocks_n = (N + TPB - 1) / TPB;

    k_prep<<<blocks_n, TPB>>>(inv_lattices, forces, N, A);

    if (O == 48) {
        long long total = (long long)N * 12;
        int blocks = (int)((total + TPB - 1) / TPB);
        k_scatterT<48><<<blocks, TPB>>>(general_ops, symm_map, N);
    } else if (O == 32) {
        long long total = (long long)N * 8;
        int blocks = (int)((total + TPB - 1) / TPB);
        k_scatterT<32><<<blocks, TPB>>>(general_ops, symm_map, N);
    } else if (O == 64) {
        long long total = (long long)N * 16;
        int blocks = (int)((total + TPB - 1) / TPB);
        k_scatterT<64><<<blocks, TPB>>>(general_ops, symm_map, N);
    } else if ((O & 3) == 0) {
        long long total = (long long)N * (O >> 2);
        int blocks = (int)((total + TPB - 1) / TPB);
        k_scatter4<<<blocks, TPB>>>(general_ops, symm_map, N, O);
    } else {
        long long total = (long long)N * O;
        int blocks = (int)((total + TPB - 1) / TPB);
        k_scatter1<<<blocks, TPB>>>(general_ops, symm_map, N, O);
    }

    k_final<<<blocks_n, TPB>>>(lattices, out, N, A, 1.0f / (float)O);
}

// round 14
// speedup vs baseline: 1.0514x; 1.0082x over previous
#include <cuda_runtime.h>
#include <cstdint>

// ---------------------------------------------------------------------------
// SymmetrizeRotavg — converged structure (best: 254.5us at R13).
//   scaled[n]   = inv_lat[b(n)]^T @ forces[n]
//   acc[symm_map[n,o]] += rot[o] @ scaled[n]   (o = 0..O-1)
//   out[n]      = lat[b(n)]^T @ (acc[n] / O)
//
// Scatter near the B300 spread-REDG floor (50.3M red.v4 lanes x 1.29
// cyc/lane / 148 SMs), but R12/R13 showed per-thread integer work is
// PARTIALLY EXPOSED (templated divisors: -2.5us; templated O: -3.1us).
// R14 continues: 32-bit index arithmetic (total = N*O/4 < 2^31) and the
// per-red cvta hoisted to one base-address conversion per thread.
// Other findings: float4 smem rot = bank-conflict disaster (R3); coarsening
// short memory kernels loses (R3/R7/R10); periphery variants all tied.
// ---------------------------------------------------------------------------

#define MAX_N (1 << 20)   // N = 1,048,576 for this problem
#define MAX_O 64

__device__ float4 g_scaled[MAX_N];
__device__ float4 g_acc[MAX_N];

// Stage 1: scaled = inv_lat^T f ; zero the accumulator (every launch, so
// graph replays are deterministic). One atom per thread.
__global__ __launch_bounds__(256) void k_prep(
    const float* __restrict__ inv_lat,
    const float* __restrict__ forces,
    int N, int A)
{
    int n = blockIdx.x * blockDim.x + threadIdx.x;
    if (n >= N) return;
    int b = n / A;
    float f0 = forces[3 * n + 0];
    float f1 = forces[3 * n + 1];
    float f2 = forces[3 * n + 2];
    const float* M = inv_lat + 9 * b;   // M[j*3+i]
    float s0 = M[0] * f0 + M[3] * f1 + M[6] * f2;
    float s1 = M[1] * f0 + M[4] * f1 + M[7] * f2;
    float s2 = M[2] * f0 + M[5] * f1 + M[8] * f2;
    g_scaled[n] = make_float4(s0, s1, s2, 0.0f);
    g_acc[n]    = make_float4(0.0f, 0.0f, 0.0f, 0.0f);
}

// red on a precomputed GLOBAL address (cvta hoisted to caller).
__device__ __forceinline__ void red_add_v4_g(uint64_t gaddr, float x, float y, float z)
{
    asm volatile(
        "red.global.add.v4.f32 [%0], {%1, %2, %3, %4};"
        :: "l"(gaddr), "f"(x), "f"(y), "f"(z), "f"(0.0f)
        : "memory");
}

__device__ __forceinline__ void red_add_v4(float4* p, float x, float y, float z)
{
    asm volatile(
        "{\n\t"
        ".reg .u64 ga;\n\t"
        "cvta.to.global.u64 ga, %0;\n\t"
        "red.global.add.v4.f32 [ga], {%1, %2, %3, %4};\n\t"
        "}"
        :: "l"(p), "f"(x), "f"(y), "f"(z), "f"(0.0f)
        : "memory");
}

__device__ __forceinline__ uint64_t to_global_u64(const void* p)
{
    uint64_t g;
    asm("cvta.to.global.u64 %0, %1;" : "=l"(g) : "l"(p));
    return g;
}

// Stage 2 (floor-pinned): one thread = one n and 4 consecutive ops.
// O compile-time; ALL index math 32-bit (N*PER_N < 2^31); one cvta per
// thread (g_acc base), targets addressed via IMAD.WIDE on tgt*16.
// Scalar smem rot loads (bank-conflict free), coalesced int4 smap load.
template<int O>
__global__ __launch_bounds__(256) void k_scatterT(
    const float* __restrict__ gops,   // (O,4,4)
    const int*   __restrict__ smap,   // (N,O)
    int N)
{
    constexpr int PER_N = O / 4;
    __shared__ float srot[O * 9];
#pragma unroll
    for (int t = threadIdx.x; t < O * 9; t += 256) {
        int o = t / 9;
        int e = t - o * 9;
        int i = e / 3;
        int j = e - i * 3;
        srot[t] = __ldg(gops + o * 16 + i * 4 + j);
    }
    __syncthreads();

    unsigned int idx = blockIdx.x * 256u + threadIdx.x;   // < N*PER_N < 2^31
    unsigned int total = (unsigned int)N * PER_N;
    if (idx >= total) return;
    unsigned int n = idx / PER_N;            // 32-bit const-div -> IMAD.HI+shift
    unsigned int k = idx - n * PER_N;

    float4 s = g_scaled[n];
    int4 t4 = *reinterpret_cast<const int4*>(smap + (size_t)n * O + k * 4);

    uint64_t acc_base = to_global_u64(g_acc);

#pragma unroll
    for (int r = 0; r < 4; r++) {
        int o = k * 4 + r;
        const float* R = srot + o * 9;   // R[i*3+j]
        float x = R[0] * s.x + R[1] * s.y + R[2] * s.z;
        float y = R[3] * s.x + R[4] * s.y + R[5] * s.z;
        float z = R[6] * s.x + R[7] * s.y + R[8] * s.z;
        int tgt = (r == 0) ? t4.x : (r == 1) ? t4.y : (r == 2) ? t4.z : t4.w;
        uint64_t gaddr = acc_base + ((uint64_t)(unsigned int)tgt << 4);
        red_add_v4_g(gaddr, x, y, z);
    }
}

// Runtime-O variant (O multiple of 4 but not 32/48/64).
__global__ __launch_bounds__(256) void k_scatter4(
    const float* __restrict__ gops,
    const int*   __restrict__ smap,
    int N, int O)
{
    __shared__ float srot[MAX_O * 9];
    for (int t = threadIdx.x; t < O * 9; t += blockDim.x) {
        int o = t / 9;
        int e = t - o * 9;
        int i = e / 3;
        int j = e - i * 3;
        srot[t] = gops[o * 16 + i * 4 + j];
    }
    __syncthreads();

    int per_n = O >> 2;
    long long idx = (long long)blockIdx.x * blockDim.x + threadIdx.x;
    long long total = (long long)N * per_n;
    if (idx >= total) return;
    int n = (int)(idx / per_n);
    int k = (int)(idx - (long long)n * per_n);

    float4 s = g_scaled[n];
    int4 t4 = *reinterpret_cast<const int4*>(smap + (long long)n * O + k * 4);
    int tgt[4] = { t4.x, t4.y, t4.z, t4.w };

#pragma unroll
    for (int r = 0; r < 4; r++) {
        int o = k * 4 + r;
        const float* R = srot + o * 9;
        float x = R[0] * s.x + R[1] * s.y + R[2] * s.z;
        float y = R[3] * s.x + R[4] * s.y + R[5] * s.z;
        float z = R[6] * s.x + R[7] * s.y + R[8] * s.z;
        red_add_v4(&g_acc[tgt[r]], x, y, z);
    }
}

// Fallback (O not a multiple of 4): one thread per (n,o).
__global__ __launch_bounds__(256) void k_scatter1(
    const float* __restrict__ gops,
    const int*   __restrict__ smap,
    int N, int O)
{
    __shared__ float srot[MAX_O * 9];
    for (int t = threadIdx.x; t < O * 9; t += blockDim.x) {
        int o = t / 9;
        int e = t - o * 9;
        int i = e / 3;
        int j = e - i * 3;
        srot[t] = gops[o * 16 + i * 4 + j];
    }
    __syncthreads();

    long long idx = (long long)blockIdx.x * blockDim.x + threadIdx.x;
    long long total = (long long)N * O;
    if (idx >= total) return;
    int n = (int)(idx / O);
    int o = (int)(idx - (long long)n * O);

    float4 s = g_scaled[n];
    int tgt = smap[(long long)n * O + o];
    const float* R = srot + o * 9;
    float x = R[0] * s.x + R[1] * s.y + R[2] * s.z;
    float y = R[3] * s.x + R[4] * s.y + R[5] * s.z;
    float z = R[6] * s.x + R[7] * s.y + R[8] * s.z;
    red_add_v4(&g_acc[tgt], x, y, z);
}

// Stage 3: out = lat^T (acc / O). One atom per thread (acc is L2-hot).
__global__ __launch_bounds__(256) void k_final(
    const float* __restrict__ lat,
    float* __restrict__ out,
    int N, int A, float inv_count)
{
    int n = blockIdx.x * blockDim.x + threadIdx.x;
    if (n >= N) return;
    int b = n / A;
    float4 a = g_acc[n];
    float s0 = a.x * inv_count;
    float s1 = a.y * inv_count;
    float s2 = a.z * inv_count;
    const float* L = lat + 9 * b;   // L[j*3+i]
    out[3 * n + 0] = L[0] * s0 + L[3] * s1 + L[6] * s2;
    out[3 * n + 1] = L[1] * s0 + L[4] * s1 + L[7] * s2;
    out[3 * n + 2] = L[2] * s0 + L[5] * s1 + L[8] * s2;
}

extern "C" void kernel_launch(void* const* d_in, const int* in_sizes, int n_in,
                              void* d_out, int out_size)
{
    const float* lattices     = (const float*)d_in[0];  // (B,3,3)
    const float* inv_lattices = (const float*)d_in[1];  // (B,3,3)
    const float* forces       = (const float*)d_in[2];  // (N,3)
    // d_in[3] = num_atoms (int64, uniform A)
    const float* general_ops  = (const float*)d_in[4];  // (O,4,4)
    const int*   symm_map     = (const int*)d_in[5];    // (N,O)
    // d_in[6] = num_general_ops (int64, uniform O)

    int B = in_sizes[0] / 9;
    int N = in_sizes[2] / 3;
    int O = in_sizes[4] / 16;
    int A = N / B;

    float* out = (float*)d_out;

    const int TPB = 256;
    int blocks_n = (N + TPB - 1) / TPB;

    k_prep<<<blocks_n, TPB>>>(inv_lattices, forces, N, A);

    // 32-bit templated path requires N*(O/4) < 2^31 (true here: 12.6M).
    long long total4 = (long long)N * (O >> 2);
    bool fits32 = total4 < 0x7FFFFFFFLL;

    if (O == 48 && fits32) {
        int blocks = (int)((total4 + TPB - 1) / TPB);
        k_scatterT<48><<<blocks, TPB>>>(general_ops, symm_map, N);
    } else if (O == 32 && fits32) {
        int blocks = (int)((total4 + TPB - 1) / TPB);
        k_scatterT<32><<<blocks, TPB>>>(general_ops, symm_map, N);
    } else if (O == 64 && fits32) {
        int blocks = (int)((total4 + TPB - 1) / TPB);
        k_scatterT<64><<<blocks, TPB>>>(general_ops, symm_map, N);
    } else if ((O & 3) == 0) {
        int blocks = (int)((total4 + TPB - 1) / TPB);
        k_scatter4<<<blocks, TPB>>>(general_ops, symm_map, N, O);
    } else {
        long long total = (long long)N * O;
        int blocks = (int)((total + TPB - 1) / TPB);
        k_scatter1<<<blocks, TPB>>>(general_ops, symm_map, N, O);
    }

    k_final<<<blocks_n, TPB>>>(lattices, out, N, A, 1.0f / (float)O);
}